// round 16
// baseline (speedup 1.0000x reference)
#include <cuda_runtime.h>
#include <cuda_fp16.h>
#include <cstdint>
#include <cstddef>

#define NN 50000
#define NE 800000
#define INDIM 256
#define HID 256
#define OUTD 64
#define NH 4

#define SWZ(o) ((o) ^ (((o) >> 3) & 0x70))

// ---------------- device scratch (static allocation only) ----------------
__device__ int   g_deg[NN];
__device__ int   g_cursor[NN];
__device__ int   g_rowptr[NN + 1];
__device__ int   g_edst[NE];
__device__ float g_eelem[NE];
__device__ __align__(16) __half g_featsh[(size_t)NN * NH * OUTD]; // [n][h][64] fp16
__device__ __align__(16) float g_ssrc[NN * NH];                   // [n][h]
__device__ __align__(16) float g_sdst[NN * NH];                   // [n][h]
// fragment-packed fp16 weights: [h][kstep][nb2][lane][w] uint32 (fp16x2)
__device__ __align__(16) uint32_t g_b1pk[4 * 16 * 16 * 32 * 4];  // 512KB
__device__ __align__(16) uint32_t g_b2pk[4 * 16 * 4 * 32 * 4];   // 128KB

// ---------------- helpers ----------------
__device__ __forceinline__ uint32_t smem_u32(const void* p) {
    uint32_t a;
    asm("{ .reg .u64 t; cvta.to.shared.u64 t, %1; cvt.u32.u64 %0, t; }" : "=r"(a) : "l"(p));
    return a;
}
__device__ __forceinline__ uint32_t pkf(float a, float b) {
    __half2 t = __floats2half2_rn(a, b);
    return reinterpret_cast<uint32_t&>(t);
}
__device__ __forceinline__ void ldsm4(uint32_t* r, uint32_t addr) {
    asm volatile("ldmatrix.sync.aligned.m8n8.x4.shared.b16 {%0,%1,%2,%3}, [%4];"
                 : "=r"(r[0]), "=r"(r[1]), "=r"(r[2]), "=r"(r[3]) : "r"(addr));
}
__device__ __forceinline__ void mma16816(float* c, const uint32_t* a, uint32_t b0, uint32_t b1) {
    asm volatile("mma.sync.aligned.m16n8k16.row.col.f32.f16.f16.f32 "
                 "{%0,%1,%2,%3}, {%4,%5,%6,%7}, {%8,%9}, {%0,%1,%2,%3};"
                 : "+f"(c[0]), "+f"(c[1]), "+f"(c[2]), "+f"(c[3])
                 : "r"(a[0]), "r"(a[1]), "r"(a[2]), "r"(a[3]), "r"(b0), "r"(b1));
}
__device__ __forceinline__ void cpasync16(uint32_t smem_addr, const void* gptr) {
    asm volatile("cp.async.cg.shared.global [%0], [%1], 16;"
                 :: "r"(smem_addr), "l"(gptr) : "memory");
}
#define CP_COMMIT() asm volatile("cp.async.commit_group;" ::: "memory")
#define CP_WAIT1()  asm volatile("cp.async.wait_group 1;" ::: "memory")

// ---------------- idx dtype sniff ----------------
__device__ __forceinline__ bool idx_is64(const int* p) {
    return (p[1] | p[3] | p[5] | p[7]) == 0;
}
__device__ __forceinline__ int load_src(const void* idx, int e, bool is64) {
    return is64 ? (int)((const long long*)idx)[e] : ((const int*)idx)[e];
}
__device__ __forceinline__ int load_dst(const void* idx, int e, bool is64) {
    return is64 ? (int)((const long long*)idx)[NE + e] : ((const int*)idx)[NE + e];
}

// ---------------- CSR: zero ----------------
__global__ void k_zero() {
    int i = blockIdx.x * blockDim.x + threadIdx.x;
    if (i < NN) { g_deg[i] = 0; g_cursor[i] = 0; }
}

// ---------------- merged: histogram + weight prep ----------------
#define HIST_BLOCKS 3125
__global__ void k_histprep(const void* __restrict__ idx,
                           const float* __restrict__ W1,
                           const float* __restrict__ W2) {
    int b = blockIdx.x;
    int t = threadIdx.x;
    if (b < HIST_BLOCKS) {
        bool is64 = idx_is64((const int*)idx);
        int e = b * 256 + t;
        if (e < NE) atomicAdd(&g_deg[load_src(idx, e, is64)], 1);
        return;
    }
    int i = (b - HIST_BLOCKS) * 256 + t;
    if (i < 131072) {
        int h = i >> 15;
        int rem = i & 32767;
        int kstep = rem >> 11;
        int rem3 = rem & 2047;
        int nb2 = rem3 >> 7;
        int rem4 = rem3 & 127;
        int lane = rem4 >> 2;
        int w = rem4 & 3;
        int n = nb2 * 16 + ((w >> 1) << 3) + (lane >> 2);
        int k = (kstep << 4) + ((lane & 3) << 1) + ((w & 1) << 3);
        float f0 = W1[((h << 8) + k) * 256 + n];
        float f1 = W1[((h << 8) + k + 1) * 256 + n];
        g_b1pk[i] = pkf(f0, f1);
    } else if (i < 131072 + 32768) {
        int j = i - 131072;
        int h = j >> 13;
        int rem = j & 8191;
        int kstep = rem >> 9;
        int rem3 = rem & 511;
        int nb2 = rem3 >> 7;
        int rem4 = rem3 & 127;
        int lane = rem4 >> 2;
        int w = rem4 & 3;
        int n = nb2 * 16 + ((w >> 1) << 3) + (lane >> 2);
        int k = (kstep << 4) + ((lane & 3) << 1) + ((w & 1) << 3);
        float f0 = W2[((h << 8) + k) * 64 + n];
        float f1 = W2[((h << 8) + k + 1) * 64 + n];
        g_b2pk[j] = pkf(f0, f1);
    }
}

// ---------------- CSR: scan ----------------
__global__ void k_scan() {
    __shared__ int sm[1024];
    const int CH = 49;
    int t = threadIdx.x;
    int base = t * CH, s = 0;
    for (int i = 0; i < CH; i++) { int g = base + i; if (g < NN) s += g_deg[g]; }
    sm[t] = s;
    __syncthreads();
    for (int off = 1; off < 1024; off <<= 1) {
        int v = (t >= off) ? sm[t - off] : 0;
        __syncthreads();
        sm[t] += v;
        __syncthreads();
    }
    int run = sm[t] - s;
    for (int i = 0; i < CH; i++) {
        int g = base + i;
        if (g <= NN) g_rowptr[g] = run;
        if (g < NN)  run += g_deg[g];
    }
}

// ---------------- fused MLP (y==0) + CSR scatter (y==1) ----------------
// SMEM: X fp16 (32KB) | hidden/fs (32KB) | B1 ring: 3 slots x 16KB (48KB) = 112KB
static constexpr uint32_t SM_H   = 32768;
static constexpr uint32_t SM_B   = 65536;
static constexpr uint32_t SM_TOT = 114688;
#define FGRID 782

__global__ __launch_bounds__(256, 2) void k_fused(const float* __restrict__ X,
                                                  const float* __restrict__ b1,
                                                  const float* __restrict__ b2,
                                                  const float* __restrict__ aw,
                                                  const float* __restrict__ ab,
                                                  const void* __restrict__ idx,
                                                  const float* __restrict__ elem) {
    // ----- scatter blocks -----
    if (blockIdx.y == 1) {
        bool is64 = idx_is64((const int*)idx);
        int gt = blockIdx.x * 256 + threadIdx.x;
        for (int e = gt; e < NE; e += FGRID * 256) {
            int s = load_src(idx, e, is64);
            int pos = g_rowptr[s] + atomicAdd(&g_cursor[s], 1);
            g_edst[pos]  = load_dst(idx, e, is64);
            g_eelem[pos] = elem[e];
        }
        return;
    }

    extern __shared__ char smem[];
    const uint32_t sb = smem_u32(smem);
    const int tid  = threadIdx.x;
    const int lane = tid & 31;
    const int wid  = tid >> 5;
    const int m0   = blockIdx.x * 64;

    const int quad = lane >> 3;
    const uint32_t rowoff = ((quad & 1) << 3) | (lane & 7);
    const uint32_t kboff  = (quad >> 1) << 4;

    // chunk copy: 16KB contiguous (2 ks of B1[h]) into ring slot c%3
    auto issue_chunk = [&](int h, int c) {
        const char* src = (const char*)g_b1pk + (size_t)h * 131072 + (size_t)c * 16384 + tid * 16;
        uint32_t dst = sb + SM_B + (uint32_t)((c % 3) * 16384) + (uint32_t)(tid * 16);
#pragma unroll
        for (int r = 0; r < 4; r++)
            cpasync16(dst + r * 4096, src + r * 4096);
        CP_COMMIT();
    };

    // ---- stage X (fp16) into SMEM once: 64 rows x 256 cols ----
    {
        const int row = tid >> 2;                // 0..63
        const int kh  = (tid & 3) << 6;          // 0,64,128,192
        const bool rok = (m0 + row) < NN;
        const float* xr = X + (size_t)(m0 + row) * INDIM + kh;
        const uint32_t slab = (uint32_t)(kh >> 6) * 8192u;
#pragma unroll
        for (int c8 = 0; c8 < 8; c8++) {
            float4 v0, v1;
            if (rok) {
                v0 = *(const float4*)(xr + c8 * 8);
                v1 = *(const float4*)(xr + c8 * 8 + 4);
            } else {
                v0 = make_float4(0.f, 0.f, 0.f, 0.f);
                v1 = v0;
            }
            uint32_t off = slab + SWZ((uint32_t)((row << 7) | (c8 << 4)));
            *(uint4*)(smem + off) =
                make_uint4(pkf(v0.x, v0.y), pkf(v0.z, v0.w), pkf(v1.x, v1.y), pkf(v1.z, v1.w));
        }
    }
    // prologue prefetch for head 0 (ring slots 0,1)
    issue_chunk(0, 0);
    issue_chunk(0, 1);
    __syncthreads();

    const int mi = wid >> 2, ni = wid & 3;       // warp tile: 32 rows x 64 cols

    for (int h = 0; h < NH; h++) {
        // ---- GEMM1: C1[64x256] = X @ W1[h], B via cp.async ring ----
        float acc[2][8][4];
#pragma unroll
        for (int a = 0; a < 2; a++)
#pragma unroll
            for (int b = 0; b < 8; b++)
#pragma unroll
                for (int c = 0; c < 4; c++) acc[a][b][c] = 0.f;

#pragma unroll 1
        for (int c = 0; c < 8; c++) {
            CP_WAIT1();
            __syncthreads();                     // chunk c visible to all warps
            const char* bsl = smem + SM_B + (c % 3) * 16384;
#pragma unroll
            for (int ks2 = 0; ks2 < 2; ks2++) {
                const int ks = c * 2 + ks2;
                uint4 bh[4];
#pragma unroll
                for (int q = 0; q < 4; q++)
                    bh[q] = *(const uint4*)(bsl + ks2 * 8192 + ((ni * 4 + q) * 32 + lane) * 16);
                const uint32_t kb = ((uint32_t)(ks & 3) << 5) | kboff;
                const uint32_t slab = (uint32_t)(ks >> 2) * 8192u;
                uint32_t a[2][4];
#pragma unroll
                for (int mf = 0; mf < 2; mf++)
                    ldsm4(a[mf], sb + slab + SWZ((uint32_t)(((mi * 32 + mf * 16 + rowoff) << 7)) | kb));
#pragma unroll
                for (int mf = 0; mf < 2; mf++)
#pragma unroll
                    for (int q = 0; q < 4; q++) {
                        mma16816(acc[mf][q * 2 + 0], a[mf], bh[q].x, bh[q].y);
                        mma16816(acc[mf][q * 2 + 1], a[mf], bh[q].z, bh[q].w);
                    }
            }
            if (c < 6) issue_chunk(h, c + 2);    // overwrites slot of chunk c-1 (consumed)
        }
        __syncthreads();   // A: ring slots 0,1 reads done; prior-head fs reads done

        // prologue prefetch for next head (hidden under epilogue1+GEMM2)
        if (h < NH - 1) {
            issue_chunk(h + 1, 0);
            issue_chunk(h + 1, 1);
        }

        // ---- epilogue1: bias + relu + fp16 -> hidden buffer ----
#pragma unroll
        for (int j = 0; j < 8; j++) {
            int n = ni * 64 + (j >> 1) * 16 + (j & 1) * 8 + ((lane & 3) << 1);
            float bv0 = __ldg(&b1[(h << 8) + n]);
            float bv1 = __ldg(&b1[(h << 8) + n + 1]);
            uint32_t kslab = SM_H + (uint32_t)(n >> 6) * 8192u;
            uint32_t cb = (uint32_t)(n & 63) << 1;
#pragma unroll
            for (int mf = 0; mf < 2; mf++) {
#pragma unroll
                for (int rr = 0; rr < 2; rr++) {
                    int row = mi * 32 + mf * 16 + (lane >> 2) + rr * 8;
                    float v0 = acc[mf][j][rr * 2]     + bv0;
                    float v1 = acc[mf][j][rr * 2 + 1] + bv1;
                    v0 = v0 > 0.f ? v0 : 0.f;
                    v1 = v1 > 0.f ? v1 : 0.f;
                    *(uint32_t*)(smem + kslab + SWZ((uint32_t)((row << 7)) | cb)) = pkf(v0, v1);
                }
            }
        }
        __syncthreads();   // B: hidden visible

        // ---- GEMM2: C2[64x64] = hidden @ W2[h] (fp16, B from L2) ----
        float c2[2][2][4];
#pragma unroll
        for (int a = 0; a < 2; a++)
#pragma unroll
            for (int b = 0; b < 2; b++)
#pragma unroll
                for (int c = 0; c < 4; c++) c2[a][b][c] = 0.f;
        {
            const uint4* bp = (const uint4*)g_b2pk + (size_t)h * 2048 + ni * 32 + lane;
#pragma unroll 4
            for (int ks = 0; ks < 16; ks++) {
                uint4 bh = bp[ks * 128];
                const uint32_t kb = ((uint32_t)(ks & 3) << 5) | kboff;
                const uint32_t slab = SM_H + (uint32_t)(ks >> 2) * 8192u;
                uint32_t a[2][4];
#pragma unroll
                for (int mf = 0; mf < 2; mf++)
                    ldsm4(a[mf], sb + slab + SWZ((uint32_t)(((mi * 32 + mf * 16 + rowoff) << 7)) | kb));
#pragma unroll
                for (int mf = 0; mf < 2; mf++) {
                    mma16816(c2[mf][0], a[mf], bh.x, bh.y);
                    mma16816(c2[mf][1], a[mf], bh.z, bh.w);
                }
            }
        }
        __syncthreads();   // C: GEMM2 reads of hidden done before fs overwrite

        // ---- epilogue2: bias; store feats (fp16 global, [n][h][64]) + fp32 in SMEM ----
        float* fs = (float*)(smem + SM_H);       // [row][65] fp32
#pragma unroll
        for (int j = 0; j < 2; j++) {
            int n = ni * 16 + j * 8 + ((lane & 3) << 1);
            float bv0 = __ldg(&b2[(h << 6) + n]);
            float bv1 = __ldg(&b2[(h << 6) + n + 1]);
#pragma unroll
            for (int mf = 0; mf < 2; mf++) {
#pragma unroll
                for (int rr = 0; rr < 2; rr++) {
                    int row = mi * 32 + mf * 16 + (lane >> 2) + rr * 8;
                    float v0 = c2[mf][j][rr * 2]     + bv0;
                    float v1 = c2[mf][j][rr * 2 + 1] + bv1;
                    fs[row * 65 + n]     = v0;
                    fs[row * 65 + n + 1] = v1;
                    int gr = m0 + row;
                    if (gr < NN)
                        *(uint32_t*)(g_featsh + ((size_t)gr * NH + h) * OUTD + n) = pkf(v0, v1);
                }
            }
        }
        __syncthreads();   // D: fs visible

        // ---- attention dots from fp32 feats: all 8 warps, 8 rows each ----
        {
            const float* awh = aw + h * (2 * OUTD + 1);
            float a0 = __ldg(&awh[2 * lane]);
            float a1 = __ldg(&awh[2 * lane + 1]);
            float a2 = __ldg(&awh[64 + 2 * lane]);
            float a3 = __ldg(&awh[65 + 2 * lane]);
            float bias = __ldg(&ab[h]);
#pragma unroll
            for (int r = 0; r < 8; r++) {
                int row = wid * 8 + r;
                const float* fr = fs + row * 65 + 2 * lane;
                float v0 = fr[0], v1 = fr[1];
                float s1 = v0 * a0 + v1 * a1;
                float s2 = v0 * a2 + v1 * a3;
#pragma unroll
                for (int o = 16; o; o >>= 1) {
                    s1 += __shfl_xor_sync(0xffffffffu, s1, o);
                    s2 += __shfl_xor_sync(0xffffffffu, s2, o);
                }
                int m = m0 + row;
                if (lane == 0 && m < NN) {
                    g_ssrc[m * NH + h] = s1 + bias;
                    g_sdst[m * NH + h] = s2;
                }
            }
        }
        // no barrier: next head's chunk-0 barrier orders fs reads before SM_H overwrite
    }
}

// ---------------- edge aggregation: warp per node, all 4 heads ----------------
__global__ __launch_bounds__(256) void k_pool(float* __restrict__ out,
                                              const float* __restrict__ aw) {
    int lane = threadIdx.x & 31;
    int n = blockIdx.x * 8 + (threadIdx.x >> 5);
    if (n >= NN) return;

    int s = g_rowptr[n];
    int e = g_rowptr[n + 1];
    float4 base = *(const float4*)&g_ssrc[n * NH];
    float aw0 = __ldg(&aw[0 * 129 + 128]);
    float aw1 = __ldg(&aw[1 * 129 + 128]);
    float aw2 = __ldg(&aw[2 * 129 + 128]);
    float aw3 = __ldg(&aw[3 * 129 + 128]);
    const __half2* fp = (const __half2*)g_featsh;   // [(n*4+h)*32 + lane]

    float ax0 = 0.f, ay0 = 0.f, ws0 = 0.f;
    float ax1 = 0.f, ay1 = 0.f, ws1 = 0.f;
    float ax2 = 0.f, ay2 = 0.f, ws2 = 0.f;
    float ax3 = 0.f, ay3 = 0.f, ws3 = 0.f;

    for (int i = s; i < e; i++) {
        int d    = g_edst[i];
        float el = g_eelem[i];
        float4 sd = *(const float4*)&g_sdst[(size_t)d * NH];
        const __half2* fd = fp + (size_t)d * (NH * 32) + lane;
        __half2 q0 = fd[0];
        __half2 q1 = fd[32];
        __half2 q2 = fd[64];
        __half2 q3 = fd[96];
        float w0 = __expf(base.x + sd.x + el * aw0);
        float w1 = __expf(base.y + sd.y + el * aw1);
        float w2 = __expf(base.z + sd.z + el * aw2);
        float w3 = __expf(base.w + sd.w + el * aw3);
        float2 f0 = __half22float2(q0), f1 = __half22float2(q1);
        float2 f2 = __half22float2(q2), f3 = __half22float2(q3);
        ax0 = fmaf(w0, f0.x, ax0); ay0 = fmaf(w0, f0.y, ay0); ws0 += w0;
        ax1 = fmaf(w1, f1.x, ax1); ay1 = fmaf(w1, f1.y, ay1); ws1 += w1;
        ax2 = fmaf(w2, f2.x, ax2); ay2 = fmaf(w2, f2.y, ay2); ws2 += w2;
        ax3 = fmaf(w3, f3.x, ax3); ay3 = fmaf(w3, f3.y, ay3); ws3 += w3;
    }

    float* o = out + (size_t)n * (NH * OUTD) + 2 * lane;
    *(float2*)(o)       = make_float2(ax0 / ws0, ay0 / ws0);
    *(float2*)(o + 64)  = make_float2(ax1 / ws1, ay1 / ws1);
    *(float2*)(o + 128) = make_float2(ax2 / ws2, ay2 / ws2);
    *(float2*)(o + 192) = make_float2(ax3 / ws3, ay3 / ws3);
}

// ---------------- launch ----------------
extern "C" void kernel_launch(void* const* d_in, const int* in_sizes, int n_in,
                              void* d_out, int out_size) {
    const float* x    = (const float*)d_in[0];
    const void*  idx  = d_in[1];
    const float* elem = (const float*)d_in[2];
    const float* W1   = (const float*)d_in[3];
    const float* b1   = (const float*)d_in[4];
    const float* W2   = (const float*)d_in[5];
    const float* b2   = (const float*)d_in[6];
    const float* aw   = (const float*)d_in[7];
    const float* ab   = (const float*)d_in[8];
    float* out = (float*)d_out;

    cudaFuncSetAttribute(k_fused, cudaFuncAttributeMaxDynamicSharedMemorySize, SM_TOT);

    k_zero<<<(NN + 255) / 256, 256>>>();
    k_histprep<<<HIST_BLOCKS + (131072 + 32768 + 255) / 256, 256>>>(idx, W1, W2);
    k_scan<<<1, 1024>>>();

    // fused MLP (y==0, head loop) + CSR scatter (y==1)
    dim3 gf(FGRID, 2);
    k_fused<<<gf, 256, SM_TOT>>>(x, b1, b2, aw, ab, idx, elem);

    // aggregation (warp per node, 4 heads)
    k_pool<<<(NN + 7) / 8, 256>>>(out, aw);
}

// round 17
// speedup vs baseline: 1.1004x; 1.1004x over previous
#include <cuda_runtime.h>
#include <cuda_fp16.h>
#include <cstdint>
#include <cstddef>

#define NN 50000
#define NE 800000
#define INDIM 256
#define HID 256
#define OUTD 64
#define NH 4

#define SWZ(o) ((o) ^ (((o) >> 3) & 0x70))

// ---------------- device scratch (static allocation only) ----------------
__device__ int   g_deg[NN];
__device__ int   g_cursor[NN];
__device__ int   g_rowptr[NN + 1];
__device__ int   g_edst[NE];
__device__ float g_eelem[NE];
__device__ __align__(16) __half g_featsh[(size_t)NN * NH * OUTD]; // [n][h][64] fp16
__device__ __align__(16) float g_ssrc[NN * NH];                   // [n][h]
__device__ __align__(16) float g_sdst[NN * NH];                   // [n][h]
// fragment-packed fp16 weights: [h][kstep][nb2][lane][w] uint32 (fp16x2)
__device__ __align__(16) uint32_t g_b1pk[4 * 16 * 16 * 32 * 4];  // 512KB
__device__ __align__(16) uint32_t g_b2pk[4 * 16 * 4 * 32 * 4];   // 128KB

// ---------------- helpers ----------------
__device__ __forceinline__ uint32_t smem_u32(const void* p) {
    uint32_t a;
    asm("{ .reg .u64 t; cvta.to.shared.u64 t, %1; cvt.u32.u64 %0, t; }" : "=r"(a) : "l"(p));
    return a;
}
__device__ __forceinline__ uint32_t pkf(float a, float b) {
    __half2 t = __floats2half2_rn(a, b);
    return reinterpret_cast<uint32_t&>(t);
}
__device__ __forceinline__ void ldsm4(uint32_t* r, uint32_t addr) {
    asm volatile("ldmatrix.sync.aligned.m8n8.x4.shared.b16 {%0,%1,%2,%3}, [%4];"
                 : "=r"(r[0]), "=r"(r[1]), "=r"(r[2]), "=r"(r[3]) : "r"(addr));
}
__device__ __forceinline__ void mma16816(float* c, const uint32_t* a, uint32_t b0, uint32_t b1) {
    asm volatile("mma.sync.aligned.m16n8k16.row.col.f32.f16.f16.f32 "
                 "{%0,%1,%2,%3}, {%4,%5,%6,%7}, {%8,%9}, {%0,%1,%2,%3};"
                 : "+f"(c[0]), "+f"(c[1]), "+f"(c[2]), "+f"(c[3])
                 : "r"(a[0]), "r"(a[1]), "r"(a[2]), "r"(a[3]), "r"(b0), "r"(b1));
}

// ---------------- idx dtype sniff ----------------
__device__ __forceinline__ bool idx_is64(const int* p) {
    return (p[1] | p[3] | p[5] | p[7]) == 0;
}
__device__ __forceinline__ int load_src(const void* idx, int e, bool is64) {
    return is64 ? (int)((const long long*)idx)[e] : ((const int*)idx)[e];
}
__device__ __forceinline__ int load_dst(const void* idx, int e, bool is64) {
    return is64 ? (int)((const long long*)idx)[NE + e] : ((const int*)idx)[NE + e];
}

// ---------------- CSR: zero ----------------
__global__ void k_zero() {
    int i = blockIdx.x * blockDim.x + threadIdx.x;
    if (i < NN) { g_deg[i] = 0; g_cursor[i] = 0; }
}

// ---------------- merged: histogram + weight prep ----------------
#define HIST_BLOCKS 3125
__global__ void k_histprep(const void* __restrict__ idx,
                           const float* __restrict__ W1,
                           const float* __restrict__ W2) {
    int b = blockIdx.x;
    int t = threadIdx.x;
    if (b < HIST_BLOCKS) {
        bool is64 = idx_is64((const int*)idx);
        int e = b * 256 + t;
        if (e < NE) atomicAdd(&g_deg[load_src(idx, e, is64)], 1);
        return;
    }
    int i = (b - HIST_BLOCKS) * 256 + t;
    if (i < 131072) {
        int h = i >> 15;
        int rem = i & 32767;
        int kstep = rem >> 11;
        int rem3 = rem & 2047;
        int nb2 = rem3 >> 7;
        int rem4 = rem3 & 127;
        int lane = rem4 >> 2;
        int w = rem4 & 3;
        int n = nb2 * 16 + ((w >> 1) << 3) + (lane >> 2);
        int k = (kstep << 4) + ((lane & 3) << 1) + ((w & 1) << 3);
        float f0 = W1[((h << 8) + k) * 256 + n];
        float f1 = W1[((h << 8) + k + 1) * 256 + n];
        g_b1pk[i] = pkf(f0, f1);
    } else if (i < 131072 + 32768) {
        int j = i - 131072;
        int h = j >> 13;
        int rem = j & 8191;
        int kstep = rem >> 9;
        int rem3 = rem & 511;
        int nb2 = rem3 >> 7;
        int rem4 = rem3 & 127;
        int lane = rem4 >> 2;
        int w = rem4 & 3;
        int n = nb2 * 16 + ((w >> 1) << 3) + (lane >> 2);
        int k = (kstep << 4) + ((lane & 3) << 1) + ((w & 1) << 3);
        float f0 = W2[((h << 8) + k) * 64 + n];
        float f1 = W2[((h << 8) + k + 1) * 64 + n];
        g_b2pk[j] = pkf(f0, f1);
    }
}

// ---------------- CSR: scan ----------------
__global__ void k_scan() {
    __shared__ int sm[1024];
    const int CH = 49;
    int t = threadIdx.x;
    int base = t * CH, s = 0;
    for (int i = 0; i < CH; i++) { int g = base + i; if (g < NN) s += g_deg[g]; }
    sm[t] = s;
    __syncthreads();
    for (int off = 1; off < 1024; off <<= 1) {
        int v = (t >= off) ? sm[t - off] : 0;
        __syncthreads();
        sm[t] += v;
        __syncthreads();
    }
    int run = sm[t] - s;
    for (int i = 0; i < CH; i++) {
        int g = base + i;
        if (g <= NN) g_rowptr[g] = run;
        if (g < NN)  run += g_deg[g];
    }
}

// ---------------- fused MLP (y==0) + CSR scatter (y==1) ----------------
// SMEM: X fp16 at 0 (32KB: 4 kslabs x 8KB), hidden/fs scratch at 32KB (32KB).
static constexpr uint32_t SM_H   = 32768;
static constexpr uint32_t SM_TOT = 65536;
#define FGRID 782

__global__ __launch_bounds__(256, 2) void k_fused(const float* __restrict__ X,
                                                  const float* __restrict__ b1,
                                                  const float* __restrict__ b2,
                                                  const float* __restrict__ aw,
                                                  const float* __restrict__ ab,
                                                  const void* __restrict__ idx,
                                                  const float* __restrict__ elem) {
    // ----- scatter blocks -----
    if (blockIdx.y == 1) {
        bool is64 = idx_is64((const int*)idx);
        int gt = blockIdx.x * 256 + threadIdx.x;
        for (int e = gt; e < NE; e += FGRID * 256) {
            int s = load_src(idx, e, is64);
            int pos = g_rowptr[s] + atomicAdd(&g_cursor[s], 1);
            g_edst[pos]  = load_dst(idx, e, is64);
            g_eelem[pos] = elem[e];
        }
        return;
    }

    extern __shared__ char smem[];
    const uint32_t sb = smem_u32(smem);
    const int tid  = threadIdx.x;
    const int lane = tid & 31;
    const int wid  = tid >> 5;
    const int m0   = blockIdx.x * 64;

    const int quad = lane >> 3;
    const uint32_t rowoff = ((quad & 1) << 3) | (lane & 7);
    const uint32_t kboff  = (quad >> 1) << 4;

    // ---- stage X (fp16) into SMEM once: 64 rows x 256 cols ----
    {
        const int row = tid >> 2;                // 0..63
        const int kh  = (tid & 3) << 6;          // 0,64,128,192
        const bool rok = (m0 + row) < NN;
        const float* xr = X + (size_t)(m0 + row) * INDIM + kh;
        const uint32_t slab = (uint32_t)(kh >> 6) * 8192u;
#pragma unroll
        for (int c8 = 0; c8 < 8; c8++) {
            float4 v0, v1;
            if (rok) {
                v0 = *(const float4*)(xr + c8 * 8);
                v1 = *(const float4*)(xr + c8 * 8 + 4);
            } else {
                v0 = make_float4(0.f, 0.f, 0.f, 0.f);
                v1 = v0;
            }
            uint32_t off = slab + SWZ((uint32_t)((row << 7) | (c8 << 4)));
            *(uint4*)(smem + off) =
                make_uint4(pkf(v0.x, v0.y), pkf(v0.z, v0.w), pkf(v1.x, v1.y), pkf(v1.z, v1.w));
        }
    }
    __syncthreads();

    const int mi = wid >> 2, ni = wid & 3;       // warp tile: 32 rows x 64 cols

    for (int h = 0; h < NH; h++) {
        // ---- GEMM1: C1[64x256] = X @ W1[h] (fp16, B from L2) ----
        float acc[2][8][4];
#pragma unroll
        for (int a = 0; a < 2; a++)
#pragma unroll
            for (int b = 0; b < 8; b++)
#pragma unroll
                for (int c = 0; c < 4; c++) acc[a][b][c] = 0.f;
        {
            const uint4* bp = (const uint4*)g_b1pk + (size_t)h * 8192 + lane;
#pragma unroll 4
            for (int ks = 0; ks < 16; ks++) {
                uint4 bh[4];
#pragma unroll
                for (int q = 0; q < 4; q++)
                    bh[q] = bp[ks * 512 + (ni * 4 + q) * 32];
                const uint32_t kb = ((uint32_t)(ks & 3) << 5) | kboff;
                const uint32_t slab = (uint32_t)(ks >> 2) * 8192u;
                uint32_t a[2][4];
#pragma unroll
                for (int mf = 0; mf < 2; mf++)
                    ldsm4(a[mf], sb + slab + SWZ((uint32_t)(((mi * 32 + mf * 16 + rowoff) << 7)) | kb));
#pragma unroll
                for (int mf = 0; mf < 2; mf++)
#pragma unroll
                    for (int q = 0; q < 4; q++) {
                        mma16816(acc[mf][q * 2 + 0], a[mf], bh[q].x, bh[q].y);
                        mma16816(acc[mf][q * 2 + 1], a[mf], bh[q].z, bh[q].w);
                    }
            }
        }
        __syncthreads();   // A: prior-head fs reads done before hidden overwrite

        // ---- epilogue1: bias + relu + fp16 -> hidden buffer ----
#pragma unroll
        for (int j = 0; j < 8; j++) {
            int n = ni * 64 + (j >> 1) * 16 + (j & 1) * 8 + ((lane & 3) << 1);
            float bv0 = __ldg(&b1[(h << 8) + n]);
            float bv1 = __ldg(&b1[(h << 8) + n + 1]);
            uint32_t kslab = SM_H + (uint32_t)(n >> 6) * 8192u;
            uint32_t cb = (uint32_t)(n & 63) << 1;
#pragma unroll
            for (int mf = 0; mf < 2; mf++) {
#pragma unroll
                for (int rr = 0; rr < 2; rr++) {
                    int row = mi * 32 + mf * 16 + (lane >> 2) + rr * 8;
                    float v0 = acc[mf][j][rr * 2]     + bv0;
                    float v1 = acc[mf][j][rr * 2 + 1] + bv1;
                    v0 = v0 > 0.f ? v0 : 0.f;
                    v1 = v1 > 0.f ? v1 : 0.f;
                    *(uint32_t*)(smem + kslab + SWZ((uint32_t)((row << 7)) | cb)) = pkf(v0, v1);
                }
            }
        }
        __syncthreads();   // B: hidden visible

        // ---- GEMM2: C2[64x64] = hidden @ W2[h] (fp16, B from L2) ----
        float c2[2][2][4];
#pragma unroll
        for (int a = 0; a < 2; a++)
#pragma unroll
            for (int b = 0; b < 2; b++)
#pragma unroll
                for (int c = 0; c < 4; c++) c2[a][b][c] = 0.f;
        {
            const uint4* bp = (const uint4*)g_b2pk + (size_t)h * 2048 + ni * 32 + lane;
#pragma unroll 4
            for (int ks = 0; ks < 16; ks++) {
                uint4 bh = bp[ks * 128];
                const uint32_t kb = ((uint32_t)(ks & 3) << 5) | kboff;
                const uint32_t slab = SM_H + (uint32_t)(ks >> 2) * 8192u;
                uint32_t a[2][4];
#pragma unroll
                for (int mf = 0; mf < 2; mf++)
                    ldsm4(a[mf], sb + slab + SWZ((uint32_t)(((mi * 32 + mf * 16 + rowoff) << 7)) | kb));
#pragma unroll
                for (int mf = 0; mf < 2; mf++) {
                    mma16816(c2[mf][0], a[mf], bh.x, bh.y);
                    mma16816(c2[mf][1], a[mf], bh.z, bh.w);
                }
            }
        }
        __syncthreads();   // C: GEMM2 reads of hidden done before fs overwrite

        // ---- epilogue2: bias; store feats (fp16 global, [n][h][64]) + fp32 in SMEM ----
        float* fs = (float*)(smem + SM_H);       // [row][65] fp32
#pragma unroll
        for (int j = 0; j < 2; j++) {
            int n = ni * 16 + j * 8 + ((lane & 3) << 1);
            float bv0 = __ldg(&b2[(h << 6) + n]);
            float bv1 = __ldg(&b2[(h << 6) + n + 1]);
#pragma unroll
            for (int mf = 0; mf < 2; mf++) {
#pragma unroll
                for (int rr = 0; rr < 2; rr++) {
                    int row = mi * 32 + mf * 16 + (lane >> 2) + rr * 8;
                    float v0 = c2[mf][j][rr * 2]     + bv0;
                    float v1 = c2[mf][j][rr * 2 + 1] + bv1;
                    fs[row * 65 + n]     = v0;
                    fs[row * 65 + n + 1] = v1;
                    int gr = m0 + row;
                    if (gr < NN)
                        *(uint32_t*)(g_featsh + ((size_t)gr * NH + h) * OUTD + n) = pkf(v0, v1);
                }
            }
        }
        __syncthreads();   // D: fs visible

        // ---- attention dots from fp32 feats: all 8 warps, 8 rows each ----
        {
            const float* awh = aw + h * (2 * OUTD + 1);
            float a0 = __ldg(&awh[2 * lane]);
            float a1 = __ldg(&awh[2 * lane + 1]);
            float a2 = __ldg(&awh[64 + 2 * lane]);
            float a3 = __ldg(&awh[65 + 2 * lane]);
            float bias = __ldg(&ab[h]);
#pragma unroll
            for (int r = 0; r < 8; r++) {
                int row = wid * 8 + r;
                const float* fr = fs + row * 65 + 2 * lane;
                float v0 = fr[0], v1 = fr[1];
                float s1 = v0 * a0 + v1 * a1;
                float s2 = v0 * a2 + v1 * a3;
#pragma unroll
                for (int o = 16; o; o >>= 1) {
                    s1 += __shfl_xor_sync(0xffffffffu, s1, o);
                    s2 += __shfl_xor_sync(0xffffffffu, s2, o);
                }
                int m = m0 + row;
                if (lane == 0 && m < NN) {
                    g_ssrc[m * NH + h] = s1 + bias;
                    g_sdst[m * NH + h] = s2;
                }
            }
        }
        // no barrier: next head's barrier A orders all fs reads before SM_H overwrite
    }
}

// ---------------- edge aggregation: warp per node, all 4 heads, 2-edge unroll ----------------
__global__ __launch_bounds__(256) void k_pool(float* __restrict__ out,
                                              const float* __restrict__ aw) {
    int lane = threadIdx.x & 31;
    int n = blockIdx.x * 8 + (threadIdx.x >> 5);
    if (n >= NN) return;

    int s = g_rowptr[n];
    int e = g_rowptr[n + 1];
    float4 base = *(const float4*)&g_ssrc[n * NH];
    float aw0 = __ldg(&aw[0 * 129 + 128]);
    float aw1 = __ldg(&aw[1 * 129 + 128]);
    float aw2 = __ldg(&aw[2 * 129 + 128]);
    float aw3 = __ldg(&aw[3 * 129 + 128]);
    const __half2* fp = (const __half2*)g_featsh;   // [(n*4+h)*32 + lane]

    float ax0 = 0.f, ay0 = 0.f, ws0 = 0.f;
    float ax1 = 0.f, ay1 = 0.f, ws1 = 0.f;
    float ax2 = 0.f, ay2 = 0.f, ws2 = 0.f;
    float ax3 = 0.f, ay3 = 0.f, ws3 = 0.f;

    int i = s;
    for (; i + 2 <= e; i += 2) {
        int dA    = g_edst[i];
        int dB    = g_edst[i + 1];
        float elA = g_eelem[i];
        float elB = g_eelem[i + 1];
        float4 sdA = *(const float4*)&g_sdst[(size_t)dA * NH];
        float4 sdB = *(const float4*)&g_sdst[(size_t)dB * NH];
        const __half2* fdA = fp + (size_t)dA * (NH * 32) + lane;
        const __half2* fdB = fp + (size_t)dB * (NH * 32) + lane;
        __half2 qA0 = fdA[0],  qA1 = fdA[32], qA2 = fdA[64], qA3 = fdA[96];
        __half2 qB0 = fdB[0],  qB1 = fdB[32], qB2 = fdB[64], qB3 = fdB[96];
        float wA0 = __expf(base.x + sdA.x + elA * aw0);
        float wA1 = __expf(base.y + sdA.y + elA * aw1);
        float wA2 = __expf(base.z + sdA.z + elA * aw2);
        float wA3 = __expf(base.w + sdA.w + elA * aw3);
        float wB0 = __expf(base.x + sdB.x + elB * aw0);
        float wB1 = __expf(base.y + sdB.y + elB * aw1);
        float wB2 = __expf(base.z + sdB.z + elB * aw2);
        float wB3 = __expf(base.w + sdB.w + elB * aw3);
        float2 fA0 = __half22float2(qA0), fA1 = __half22float2(qA1);
        float2 fA2 = __half22float2(qA2), fA3 = __half22float2(qA3);
        float2 fB0 = __half22float2(qB0), fB1 = __half22float2(qB1);
        float2 fB2 = __half22float2(qB2), fB3 = __half22float2(qB3);
        ax0 = fmaf(wA0, fA0.x, ax0); ay0 = fmaf(wA0, fA0.y, ay0);
        ax1 = fmaf(wA1, fA1.x, ax1); ay1 = fmaf(wA1, fA1.y, ay1);
        ax2 = fmaf(wA2, fA2.x, ax2); ay2 = fmaf(wA2, fA2.y, ay2);
        ax3 = fmaf(wA3, fA3.x, ax3); ay3 = fmaf(wA3, fA3.y, ay3);
        ax0 = fmaf(wB0, fB0.x, ax0); ay0 = fmaf(wB0, fB0.y, ay0);
        ax1 = fmaf(wB1, fB1.x, ax1); ay1 = fmaf(wB1, fB1.y, ay1);
        ax2 = fmaf(wB2, fB2.x, ax2); ay2 = fmaf(wB2, fB2.y, ay2);
        ax3 = fmaf(wB3, fB3.x, ax3); ay3 = fmaf(wB3, fB3.y, ay3);
        ws0 += wA0 + wB0;
        ws1 += wA1 + wB1;
        ws2 += wA2 + wB2;
        ws3 += wA3 + wB3;
    }
    for (; i < e; i++) {
        int d    = g_edst[i];
        float el = g_eelem[i];
        float4 sd = *(const float4*)&g_sdst[(size_t)d * NH];
        const __half2* fd = fp + (size_t)d * (NH * 32) + lane;
        __half2 q0 = fd[0], q1 = fd[32], q2 = fd[64], q3 = fd[96];
        float w0 = __expf(base.x + sd.x + el * aw0);
        float w1 = __expf(base.y + sd.y + el * aw1);
        float w2 = __expf(base.z + sd.z + el * aw2);
        float w3 = __expf(base.w + sd.w + el * aw3);
        float2 f0 = __half22float2(q0), f1 = __half22float2(q1);
        float2 f2 = __half22float2(q2), f3 = __half22float2(q3);
        ax0 = fmaf(w0, f0.x, ax0); ay0 = fmaf(w0, f0.y, ay0); ws0 += w0;
        ax1 = fmaf(w1, f1.x, ax1); ay1 = fmaf(w1, f1.y, ay1); ws1 += w1;
        ax2 = fmaf(w2, f2.x, ax2); ay2 = fmaf(w2, f2.y, ay2); ws2 += w2;
        ax3 = fmaf(w3, f3.x, ax3); ay3 = fmaf(w3, f3.y, ay3); ws3 += w3;
    }

    float* o = out + (size_t)n * (NH * OUTD) + 2 * lane;
    *(float2*)(o)       = make_float2(ax0 / ws0, ay0 / ws0);
    *(float2*)(o + 64)  = make_float2(ax1 / ws1, ay1 / ws1);
    *(float2*)(o + 128) = make_float2(ax2 / ws2, ay2 / ws2);
    *(float2*)(o + 192) = make_float2(ax3 / ws3, ay3 / ws3);
}

// ---------------- launch ----------------
extern "C" void kernel_launch(void* const* d_in, const int* in_sizes, int n_in,
                              void* d_out, int out_size) {
    const float* x    = (const float*)d_in[0];
    const void*  idx  = d_in[1];
    const float* elem = (const float*)d_in[2];
    const float* W1   = (const float*)d_in[3];
    const float* b1   = (const float*)d_in[4];
    const float* W2   = (const float*)d_in[5];
    const float* b2   = (const float*)d_in[6];
    const float* aw   = (const float*)d_in[7];
    const float* ab   = (const float*)d_in[8];
    float* out = (float*)d_out;

    cudaFuncSetAttribute(k_fused, cudaFuncAttributeMaxDynamicSharedMemorySize, SM_TOT);

    k_zero<<<(NN + 255) / 256, 256>>>();
    k_histprep<<<HIST_BLOCKS + (131072 + 32768 + 255) / 256, 256>>>(idx, W1, W2);
    k_scan<<<1, 1024>>>();

    // fused MLP (y==0, head loop) + CSR scatter (y==1)
    dim3 gf(FGRID, 2);
    k_fused<<<gf, 256, SM_TOT>>>(x, b1, b2, aw, ab, idx, elem);

    // aggregation (warp per node, 4 heads, 2-edge unroll)
    k_pool<<<(NN + 7) / 8, 256>>>(out, aw);
}